// round 5
// baseline (speedup 1.0000x reference)
#include <cuda_runtime.h>
#include <cstdint>

// Problem constants (fixed shapes from the reference)
#define NPIX    (8 * 512 * 512)     // N*H*W = 2,097,152 (divisible by 256)
#define HW_SH   18                  // log2(512*512)
#define FCOUNT  100000
#define SIGMA_INV   10000.0f        // 1/SIGMA
#define GAMMA_INV   10000.0f        // 1/GAMMA
#define ZFARC       100.0f
#define INV_ZRANGE  (1.0f / 99.0f)  // 1/(ZFAR-ZNEAR)
#define EPSB        1e-10f

// Packed per-face records: 128B-aligned, 5 float4s used (18 floats):
//  [v0.xyz v1.x | v1.yz v2.xy | v2.z n0.xyz | n1.xyz n2.x | n2.yz - -]
__device__ float4 g_face_table[(size_t)FCOUNT * 8];   // 12.8 MB static scratch (allowed)

// ---------------------------------------------------------------------------
// Kernel 1: gather verts/normals per face into line-aligned records.
// ---------------------------------------------------------------------------
__global__ void __launch_bounds__(256)
pack_faces(const int* __restrict__ faces,
           const float* __restrict__ verts,
           const float* __restrict__ vnorm)
{
    int f = blockIdx.x * blockDim.x + threadIdx.x;
    if (f >= FCOUNT) return;
    int i0 = __ldg(faces + 3 * f + 0);
    int i1 = __ldg(faces + 3 * f + 1);
    int i2 = __ldg(faces + 3 * f + 2);

    float v0x = __ldg(verts + 3 * i0 + 0), v0y = __ldg(verts + 3 * i0 + 1), v0z = __ldg(verts + 3 * i0 + 2);
    float v1x = __ldg(verts + 3 * i1 + 0), v1y = __ldg(verts + 3 * i1 + 1), v1z = __ldg(verts + 3 * i1 + 2);
    float v2x = __ldg(verts + 3 * i2 + 0), v2y = __ldg(verts + 3 * i2 + 1), v2z = __ldg(verts + 3 * i2 + 2);
    float n0x = __ldg(vnorm + 3 * i0 + 0), n0y = __ldg(vnorm + 3 * i0 + 1), n0z = __ldg(vnorm + 3 * i0 + 2);
    float n1x = __ldg(vnorm + 3 * i1 + 0), n1y = __ldg(vnorm + 3 * i1 + 1), n1z = __ldg(vnorm + 3 * i1 + 2);
    float n2x = __ldg(vnorm + 3 * i2 + 0), n2y = __ldg(vnorm + 3 * i2 + 1), n2z = __ldg(vnorm + 3 * i2 + 2);

    float4* rec = g_face_table + (size_t)f * 8;
    rec[0] = make_float4(v0x, v0y, v0z, v1x);
    rec[1] = make_float4(v1y, v1z, v2x, v2y);
    rec[2] = make_float4(v2z, n0x, n0y, n0z);
    rec[3] = make_float4(n1x, n1y, n1z, n2x);
    rec[4] = make_float4(n2y, n2z, 0.0f, 0.0f);
}

// reference normalize: x / max(||x||, 1e-6)  ==  x * min(rsqrt(||x||^2), 1e6)
__device__ __forceinline__ float safe_rnorm(float n2)
{
    return fminf(rsqrtf(n2), 1e6f);
}

// ---------------------------------------------------------------------------
// Kernel 2: shade + softmax blend. One thread per pixel, warp-cooperative
// coalesced face-record fetch through SMEM (stride-20-float records are
// bank-conflict-free for LDS.128, and the STS side degenerates to a linear
// 16B-per-lane copy).
// ---------------------------------------------------------------------------
__global__ void __launch_bounds__(256)
shade(const float4* __restrict__ bary,     // NPIX*3 float4 (12 floats/pixel)
      const float4* __restrict__ zb,       // NPIX
      const float4* __restrict__ ds,       // NPIX
      const float4* __restrict__ tx,       // NPIX*3
      const float*  __restrict__ vis,      // NPIX*3
      const int4*   __restrict__ p2f,      // NPIX
      const float*  __restrict__ l_loc,
      const float*  __restrict__ l_amb,
      const float*  __restrict__ l_dif,
      const float*  __restrict__ l_spc,
      const float*  __restrict__ cam,
      const float*  __restrict__ m_amb,
      const float*  __restrict__ m_dif,
      const float*  __restrict__ m_spc,
      const float*  __restrict__ shin,
      float4*       __restrict__ out)
{
    __shared__ float4 s_rec[8 * 160];      // 8 warps * 32 records * 5 float4
    const int P    = blockIdx.x * 256 + threadIdx.x;   // grid covers NPIX exactly
    const int lane = threadIdx.x & 31;
    float4* s = s_rec + (threadIdx.x >> 5) * 160;
    const int n = P >> HW_SH;

    // Per-image params (warp-uniform broadcast loads)
    const float llx = __ldg(l_loc + 3 * n), lly = __ldg(l_loc + 3 * n + 1), llz = __ldg(l_loc + 3 * n + 2);
    const float ccx = __ldg(cam   + 3 * n), ccy = __ldg(cam   + 3 * n + 1), ccz = __ldg(cam   + 3 * n + 2);
    const float ambr = __ldg(m_amb + 3 * n + 0) * __ldg(l_amb + 3 * n + 0);
    const float ambg = __ldg(m_amb + 3 * n + 1) * __ldg(l_amb + 3 * n + 1);
    const float ambb = __ldg(m_amb + 3 * n + 2) * __ldg(l_amb + 3 * n + 2);
    const float kdr  = __ldg(m_dif + 3 * n + 0) * __ldg(l_dif + 3 * n + 0);
    const float kdg  = __ldg(m_dif + 3 * n + 1) * __ldg(l_dif + 3 * n + 1);
    const float kdb  = __ldg(m_dif + 3 * n + 2) * __ldg(l_dif + 3 * n + 2);
    const float ksr  = __ldg(m_spc + 3 * n + 0) * __ldg(l_spc + 3 * n + 0);
    const float ksg  = __ldg(m_spc + 3 * n + 1) * __ldg(l_spc + 3 * n + 1);
    const float ksb  = __ldg(m_spc + 3 * n + 2) * __ldg(l_spc + 3 * n + 2);
    const float sh   = __ldg(shin + n);

    // Streaming per-pixel data (vectorized)
    const int4   f4 = __ldg(p2f + P);
    const float4 z4 = __ldg(zb + P);
    const float4 d4 = __ldg(ds + P);
    const float4 q0 = __ldg(bary + 3 * P + 0);
    const float4 q1 = __ldg(bary + 3 * P + 1);
    const float4 q2 = __ldg(bary + 3 * P + 2);
    const float4 t0 = __ldg(tx + 3 * P + 0);
    const float4 t1 = __ldg(tx + 3 * P + 1);
    const float4 t2 = __ldg(tx + 3 * P + 2);
    const float  vr = __ldg(vis + 3 * P + 0);
    const float  vg = __ldg(vis + 3 * P + 1);
    const float  vb = __ldg(vis + 3 * P + 2);

    const int   fk[4]  = { f4.x, f4.y, f4.z, f4.w };
    const float zk[4]  = { z4.x, z4.y, z4.z, z4.w };
    const float dk[4]  = { d4.x, d4.y, d4.z, d4.w };
    const float bxk[4] = { q0.x, q0.w, q1.z, q2.y };
    const float byk[4] = { q0.y, q1.x, q1.w, q2.z };
    const float bzk[4] = { q0.z, q1.y, q2.x, q2.w };
    const float txr[4] = { t0.x, t0.w, t1.z, t2.y };
    const float txg[4] = { t0.y, t1.x, t1.w, t2.z };
    const float txb[4] = { t0.z, t1.y, t2.x, t2.w };

    float cr[4], cg[4], cb[4], prob[4], zi[4];

#pragma unroll
    for (int k = 0; k < 4; k++) {
        // ---- cooperative record fetch: 160 coalesced float4 loads per warp ----
        const int fc = max(fk[k], 0);
#pragma unroll
        for (int j = 0; j < 5; j++) {
            int t = j * 32 + lane;
            int r = t / 5;
            int p = t - 5 * r;
            int fr = __shfl_sync(0xffffffffu, fc, r);
            s[t] = __ldg(g_face_table + (size_t)fr * 8 + p);   // record line-aligned: 1 line/record
        }
        __syncwarp();
        const float4 a0 = s[lane * 5 + 0];
        const float4 a1 = s[lane * 5 + 1];
        const float4 a2 = s[lane * 5 + 2];
        const float4 a3 = s[lane * 5 + 3];
        const float4 a4 = s[lane * 5 + 4];
        __syncwarp();

        // ---- barycentric interpolation ----
        const float b0 = bxk[k], b1 = byk[k], b2 = bzk[k];
        const float pcx = b0 * a0.x + b1 * a0.w + b2 * a1.z;
        const float pcy = b0 * a0.y + b1 * a1.x + b2 * a1.w;
        const float pcz = b0 * a0.z + b1 * a1.y + b2 * a2.x;
        const float pnx = b0 * a2.y + b1 * a3.x + b2 * a3.w;
        const float pny = b0 * a2.z + b1 * a3.y + b2 * a4.x;
        const float pnz = b0 * a2.w + b1 * a3.z + b2 * a4.y;

        // ---- Phong shading ----
        const float rn = safe_rnorm(pnx * pnx + pny * pny + pnz * pnz);
        const float nx = pnx * rn, ny = pny * rn, nz = pnz * rn;

        float dx = llx - pcx, dy = lly - pcy, dz = llz - pcz;
        const float rd = safe_rnorm(dx * dx + dy * dy + dz * dz);
        dx *= rd; dy *= rd; dz *= rd;

        const float cosA = nx * dx + ny * dy + nz * dz;
        const float rc   = fmaxf(cosA, 0.0f);

        const float rfx = 2.0f * cosA * nx - dx;
        const float rfy = 2.0f * cosA * ny - dy;
        const float rfz = 2.0f * cosA * nz - dz;

        const float vx = ccx - pcx, vy = ccy - pcy, vz = ccz - pcz;
        const float rv = safe_rnorm(vx * vx + vy * vy + vz * vz);
        float sc = (vx * rfx + vy * rfy + vz * rfz) * rv;
        sc = fmaxf(sc, 0.0f);
        const float spec = (cosA > 0.0f && sc > 0.0f) ? __powf(sc, sh) : 0.0f;

        cr[k] = (ambr + kdr * rc * vr) * txr[k] + ksr * spec;
        cg[k] = (ambg + kdg * rc * vg) * txg[k] + ksg * spec;
        cb[k] = (ambb + kdb * rc * vb) * txb[k] + ksb * spec;

        // ---- per-fragment blend inputs (masked fragments carry weight 0) ----
        const bool m = (fk[k] >= 0);
        prob[k] = m ? __fdividef(1.0f, 1.0f + __expf(dk[k] * SIGMA_INV)) : 0.0f;
        zi[k]   = m ? (ZFARC - zk[k]) * INV_ZRANGE : 0.0f;
    }

    // ---- softmax-style z blend across K ----
    const float zmax  = fmaxf(fmaxf(fmaxf(zi[0], zi[1]), fmaxf(zi[2], zi[3])), EPSB);
    const float alpha = 1.0f - (1.0f - prob[0]) * (1.0f - prob[1]) * (1.0f - prob[2]) * (1.0f - prob[3]);

    float wsum = 0.0f, sr = 0.0f, sg = 0.0f, sb = 0.0f;
#pragma unroll
    for (int k = 0; k < 4; k++) {
        const float w = prob[k] * __expf((zi[k] - zmax) * GAMMA_INV);
        wsum += w;
        sr += w * cr[k];
        sg += w * cg[k];
        sb += w * cb[k];
    }
    const float delta = __expf((EPSB - zmax) * GAMMA_INV);
    const float inv   = 1.0f / (wsum + delta);      // BG = (1,1,1) -> delta*BG = delta

    out[P] = make_float4((sr + delta) * inv, (sg + delta) * inv, (sb + delta) * inv, alpha);
}

// ---------------------------------------------------------------------------
// Input order (metadata.txt / setup_inputs order):
//  0 verts  1 vertex_normals  2 bary_coords  3 zbuf  4 dists  5 texels
//  6 vis_maps  7 light_location  8 light_ambient  9 light_diffuse
// 10 light_specular 11 camera_center 12 mat_ambient 13 mat_diffuse
// 14 mat_specular 15 shininess 16 faces 17 pix_to_face
// ---------------------------------------------------------------------------
extern "C" void kernel_launch(void* const* d_in, const int* in_sizes, int n_in,
                              void* d_out, int out_size)
{
    (void)in_sizes; (void)n_in; (void)out_size;

    const float* verts  = (const float*)d_in[0];
    const float* vnorm  = (const float*)d_in[1];
    const float4* bary  = (const float4*)d_in[2];
    const float4* zb    = (const float4*)d_in[3];
    const float4* ds    = (const float4*)d_in[4];
    const float4* tx    = (const float4*)d_in[5];
    const float*  vis   = (const float*)d_in[6];
    const float*  l_loc = (const float*)d_in[7];
    const float*  l_amb = (const float*)d_in[8];
    const float*  l_dif = (const float*)d_in[9];
    const float*  l_spc = (const float*)d_in[10];
    const float*  cam   = (const float*)d_in[11];
    const float*  m_amb = (const float*)d_in[12];
    const float*  m_dif = (const float*)d_in[13];
    const float*  m_spc = (const float*)d_in[14];
    const float*  shin  = (const float*)d_in[15];
    const int*    faces = (const int*)d_in[16];
    const int4*   p2f   = (const int4*)d_in[17];
    float4* out = (float4*)d_out;

    pack_faces<<<(FCOUNT + 255) / 256, 256>>>(faces, verts, vnorm);
    shade<<<NPIX / 256, 256>>>(bary, zb, ds, tx, vis, p2f,
                               l_loc, l_amb, l_dif, l_spc, cam,
                               m_amb, m_dif, m_spc, shin, out);
}